// round 5
// baseline (speedup 1.0000x reference)
#include <cuda_runtime.h>
#include <cuda_fp16.h>
#include <cstdint>

// ===========================================================================
// LSTM cell = one fused f16 GEMM  g = [x|h] @ Wcat^T  (M=65536, N=2048, K=768)
// + fused gate epilogue -> h_new, c_new.
//
// N packing: n = 4*h + gate (gates adjacent) -> fully in-register LSTM epilogue
// via one lane-pair shuffle.
//
// R4: mma.sync.m16n8k16 pipeline only (toolchain emits base sm_103 PTX; no
// tcgen05 feature pass exists -> dead path removed).
// CTA tile 256x128 (was 128x128): halves per-output operand L2 traffic.
// 512 threads, 4x4 warp grid, warp tile 64x32, 4-stage cp.async K=32 pipeline.
// ===========================================================================

#define B_ROWS   65536
#define DIN      256
#define HDIM     512
#define K_TOTAL  768
#define N_TOTAL  2048

#define TM   256            // CTA M tile
#define TN   128            // CTA N tile = 32 h * 4 gates

#define FB_KC       32
#define FB_STAGES   4
#define FB_ROWB     80                      // padded row bytes (64B data + 16B pad)
#define FB_ATILEB   (TM * FB_ROWB)          // 20480
#define FB_BTILEB   (TN * FB_ROWB)          // 10240
#define FB_STAGEB   (FB_ATILEB + FB_BTILEB) // 30720
#define FB_NSTEPS   (K_TOTAL / FB_KC)       // 24

#define OFF_BIAS    64
#define OFF_TILES   1024
#define SMEM_TOTAL  (OFF_TILES + FB_STAGES * FB_STAGEB)   // 123904

// f16 scratch
__device__ __align__(128) __half g_A[(size_t)B_ROWS * K_TOTAL];   // 96 MB
__device__ __align__(128) __half g_Bw[(size_t)N_TOTAL * K_TOTAL]; // 3 MB

// ---------------------------------------------------------------------------
// helpers
// ---------------------------------------------------------------------------
__device__ __forceinline__ uint32_t smem_u32(const void* p) {
    return (uint32_t)__cvta_generic_to_shared(p);
}
__device__ __forceinline__ void cp_async16(uint32_t sdst, const void* gsrc) {
    asm volatile("cp.async.cg.shared.global [%0], [%1], 16;\n"
                 :: "r"(sdst), "l"(__cvta_generic_to_global(gsrc)));
}
__device__ __forceinline__ float fsig(float x) {
    return __fdividef(1.0f, 1.0f + __expf(-x));
}
__device__ __forceinline__ float ftanh_(float x) {
    float e = __expf(-2.0f * fabsf(x));
    float r = __fdividef(1.0f - e, 1.0f + e);
    return copysignf(r, x);
}
__device__ __forceinline__ void ldsm_x4(uint32_t& r0, uint32_t& r1,
                                        uint32_t& r2, uint32_t& r3, uint32_t a) {
    asm volatile("ldmatrix.sync.aligned.m8n8.x4.shared.b16 {%0,%1,%2,%3}, [%4];\n"
                 : "=r"(r0), "=r"(r1), "=r"(r2), "=r"(r3) : "r"(a));
}
__device__ __forceinline__ void ldsm_x2(uint32_t& r0, uint32_t& r1, uint32_t a) {
    asm volatile("ldmatrix.sync.aligned.m8n8.x2.shared.b16 {%0,%1}, [%2];\n"
                 : "=r"(r0), "=r"(r1) : "r"(a));
}
__device__ __forceinline__ void mma16816(float* c, const uint32_t* a,
                                         const uint32_t* b) {
    asm volatile(
        "mma.sync.aligned.m16n8k16.row.col.f32.f16.f16.f32 "
        "{%0,%1,%2,%3}, {%4,%5,%6,%7}, {%8,%9}, {%0,%1,%2,%3};\n"
        : "+f"(c[0]), "+f"(c[1]), "+f"(c[2]), "+f"(c[3])
        : "r"(a[0]), "r"(a[1]), "r"(a[2]), "r"(a[3]), "r"(b[0]), "r"(b[1]));
}

// load one K=32 stage: A 256 rows, B 128 rows, 80B padded rows, 16B chunks
__device__ __forceinline__ void fb_load_stage(uint32_t smem_base, int buf,
                                              int kc0, int tid, int m0, int n0) {
    uint32_t sA = smem_base + OFF_TILES + (uint32_t)buf * FB_STAGEB;
    uint32_t sB = sA + FB_ATILEB;
#pragma unroll
    for (int j = 0; j < 2; j++) {              // A: 1024 chunks / 512 threads
        int idx = tid + j * 512;
        int row = idx >> 2, c4 = idx & 3;
        cp_async16(sA + row * FB_ROWB + c4 * 16,
                   g_A + (size_t)(m0 + row) * K_TOTAL + kc0 + c4 * 8);
    }
    {                                           // B: 512 chunks / 512 threads
        int row = tid >> 2, c4 = tid & 3;
        cp_async16(sB + row * FB_ROWB + c4 * 16,
                   g_Bw + (size_t)(n0 + row) * K_TOTAL + kc0 + c4 * 8);
    }
    asm volatile("cp.async.commit_group;\n" ::: "memory");
}

// ---------------------------------------------------------------------------
// prep kernels: fp32 -> f16 packing
// ---------------------------------------------------------------------------
__global__ void __launch_bounds__(256) prep_A(const float* __restrict__ x,
                                              const float* __restrict__ h) {
    size_t i  = (size_t)blockIdx.x * blockDim.x + threadIdx.x;
    size_t e0 = i * 8;
    int b = (int)(e0 / K_TOTAL);
    int k = (int)(e0 % K_TOTAL);
    const float* src = (k < DIN) ? (x + (size_t)b * DIN + k)
                                 : (h + (size_t)b * HDIM + (k - DIN));
    float4 f0 = ((const float4*)src)[0];
    float4 f1 = ((const float4*)src)[1];
    __half2 p0 = __floats2half2_rn(f0.x, f0.y);
    __half2 p1 = __floats2half2_rn(f0.z, f0.w);
    __half2 p2 = __floats2half2_rn(f1.x, f1.y);
    __half2 p3 = __floats2half2_rn(f1.z, f1.w);
    uint4 o;
    o.x = *reinterpret_cast<unsigned*>(&p0);
    o.y = *reinterpret_cast<unsigned*>(&p1);
    o.z = *reinterpret_cast<unsigned*>(&p2);
    o.w = *reinterpret_cast<unsigned*>(&p3);
    *reinterpret_cast<uint4*>(g_A + e0) = o;
}

__global__ void __launch_bounds__(256) prep_B(const float* __restrict__ U,
                                              const float* __restrict__ W) {
    int t = blockIdx.x * blockDim.x + threadIdx.x;
    int k = t % K_TOTAL;
    int n = t / K_TOTAL;
    int g = n & 3;
    int hh = n >> 2;
    float v = (k < DIN) ? U[((size_t)g * DIN + k) * HDIM + hh]
                        : W[((size_t)g * HDIM + (k - DIN)) * HDIM + hh];
    g_Bw[(size_t)n * K_TOTAL + k] = __float2half_rn(v);
}

// ---------------------------------------------------------------------------
// main kernel: 256x128 GEMM tile + fused LSTM epilogue
// ---------------------------------------------------------------------------
__global__ void __launch_bounds__(512, 1)
lstm_main(const float* __restrict__ c_old, const float* __restrict__ bU,
          const float* __restrict__ bW, float* __restrict__ out) {
    extern __shared__ __align__(1024) char smem[];
    uint32_t smem_base = smem_u32(smem);
    int tid  = threadIdx.x;
    int wid  = tid >> 5;
    int lane = tid & 31;
    int h0 = blockIdx.x * (TN / 4);          // 32 h per CTA; n-block fastest
    int n0 = blockIdx.x * TN;
    int m0 = blockIdx.y * TM;

    // bias table indexed by local n column (n = 4*h + gate)
    float* sbias = reinterpret_cast<float*>(smem + OFF_BIAS);
    if (tid < TN) {
        int g  = tid & 3;
        int hg = h0 + (tid >> 2);
        sbias[tid] = bU[g * HDIM + hg] + bW[g * HDIM + hg];
    }

    int warpM = wid >> 2;                    // 0..3   (64 rows each)
    int warpN = wid & 3;                     // 0..3   (32 cols each)

    float acc[4][4][4];
#pragma unroll
    for (int a = 0; a < 4; a++)
#pragma unroll
        for (int b = 0; b < 4; b++)
#pragma unroll
            for (int c = 0; c < 4; c++) acc[a][b][c] = 0.0f;

    // ldmatrix lane address components
    int rowA  = warpM * 64 + (lane & 15);            // + ma*16
    int colAb = ((lane >> 4) << 3) * 2;              // 0 or 16 bytes
    int l16   = lane & 15;
    int rowB  = warpN * 32 + (l16 & 7);              // + na*8
    int colBb = ((l16 >> 3) & 1) * 16;               // 0 or 16 bytes

    // prologue: 3 stages in flight
    fb_load_stage(smem_base, 0, 0, tid, m0, n0);
    fb_load_stage(smem_base, 1, FB_KC, tid, m0, n0);
    fb_load_stage(smem_base, 2, 2 * FB_KC, tid, m0, n0);

#pragma unroll 1
    for (int i = 0; i < FB_NSTEPS; i++) {
        if (i <= FB_NSTEPS - 3)
            asm volatile("cp.async.wait_group 2;\n" ::: "memory");
        else if (i == FB_NSTEPS - 2)
            asm volatile("cp.async.wait_group 1;\n" ::: "memory");
        else
            asm volatile("cp.async.wait_group 0;\n" ::: "memory");
        __syncthreads();

        if (i + 3 < FB_NSTEPS)
            fb_load_stage(smem_base, (i + 3) & 3, (i + 3) * FB_KC, tid, m0, n0);

        uint32_t sA = smem_base + OFF_TILES + (uint32_t)(i & 3) * FB_STAGEB;
        uint32_t sB = sA + FB_ATILEB;
#pragma unroll
        for (int kk = 0; kk < 2; kk++) {
            uint32_t afr[4][4], bfr[4][2];
#pragma unroll
            for (int ma = 0; ma < 4; ma++)
                ldsm_x4(afr[ma][0], afr[ma][1], afr[ma][2], afr[ma][3],
                        sA + (rowA + ma * 16) * FB_ROWB + kk * 32 + colAb);
#pragma unroll
            for (int na = 0; na < 4; na++)
                ldsm_x2(bfr[na][0], bfr[na][1],
                        sB + (rowB + na * 8) * FB_ROWB + kk * 32 + colBb);
#pragma unroll
            for (int ma = 0; ma < 4; ma++)
#pragma unroll
                for (int na = 0; na < 4; na++)
                    mma16816(acc[ma][na], afr[ma], bfr[na]);
        }
    }
    __syncthreads();

    // fused epilogue: lane-pair shuffle reunites 4 gates per (row, h)
    {
        bool odd = lane & 1;
        int r_base = m0 + warpM * 64 + (lane >> 2) + (odd ? 8 : 0);
        int h_base = h0 + warpN * 8 + ((lane & 3) >> 1);
        float* outc = out + (size_t)B_ROWS * HDIM;

#pragma unroll
        for (int ma = 0; ma < 4; ma++) {
            int row = r_base + ma * 16;
#pragma unroll
            for (int na = 0; na < 4; na++) {
                int nl = warpN * 32 + na * 8 + (lane & 3) * 2;
                float d0 = acc[ma][na][0] + sbias[nl];
                float d1 = acc[ma][na][1] + sbias[nl + 1];
                float d2 = acc[ma][na][2] + sbias[nl];
                float d3 = acc[ma][na][3] + sbias[nl + 1];
                float e0 = __shfl_xor_sync(0xffffffffu, d0, 1);
                float e1 = __shfl_xor_sync(0xffffffffu, d1, 1);
                float e2 = __shfl_xor_sync(0xffffffffu, d2, 1);
                float e3 = __shfl_xor_sync(0xffffffffu, d3, 1);
                float gi = odd ? e2 : d0;
                float gf = odd ? e3 : d1;
                float go = odd ? d2 : e0;
                float gc = odd ? d3 : e1;
                int h = h_base + na * 2;
                float co = c_old[(size_t)row * HDIM + h];
                float it = fsig(gi), ft = fsig(gf), ot = fsig(go), ct = ftanh_(gc);
                float cc = fmaf(it, ct, ft * co);
                out[(size_t)row * HDIM + h]  = ot * ftanh_(cc);
                outc[(size_t)row * HDIM + h] = cc;
            }
        }
    }
}

// ---------------------------------------------------------------------------
// kernel_launch
// inputs: 0=input_x, 1=h_old, 2=c_old, 3=U, 4=bU, 5=W, 6=bW
// output: [h_new | c_new] fp32, 2*65536*512
// ---------------------------------------------------------------------------
extern "C" void kernel_launch(void* const* d_in, const int* in_sizes, int n_in,
                              void* d_out, int out_size) {
    const float* x    = (const float*)d_in[0];
    const float* hold = (const float*)d_in[1];
    const float* cold = (const float*)d_in[2];
    const float* U    = (const float*)d_in[3];
    const float* bU   = (const float*)d_in[4];
    const float* W    = (const float*)d_in[5];
    const float* bW   = (const float*)d_in[6];
    float* out = (float*)d_out;

    cudaFuncSetAttribute(lstm_main, cudaFuncAttributeMaxDynamicSharedMemorySize,
                         SMEM_TOTAL);

    {   // pack A = [x | h] -> f16
        size_t n8 = (size_t)B_ROWS * K_TOTAL / 8;
        prep_A<<<(unsigned)(n8 / 256), 256>>>(x, hold);
    }
    {   // pack Bw[n][k], n = 4*h + gate -> f16
        int nt = N_TOTAL * K_TOTAL;
        prep_B<<<nt / 256, 256>>>(U, W);
    }

    dim3 grid(N_TOTAL / TN, B_ROWS / TM, 1);   // (16, 256)
    lstm_main<<<grid, 512, SMEM_TOTAL>>>(cold, bU, bW, out);
}

// round 6
// speedup vs baseline: 1.5429x; 1.5429x over previous
#include <cuda_runtime.h>
#include <cuda_fp16.h>
#include <cstdint>

// ===========================================================================
// LSTM cell = one fused f16 GEMM  g = [x|h] @ Wcat^T  (M=65536, N=2048, K=768)
// + fused gate epilogue -> h_new, c_new.
//
// R6: CTA tile 128x256, 256 threads (8 warps, 2Mx4N), warp tile 64x64.
//  - per-output SMEM fragment traffic halved vs R3 (the 128-reg spill trap of
//    R4's 512-thread config is structurally avoided: 256 thr -> 255-reg cap)
//  - B fragments fetched with paired ldmatrix.x4 (2 n-tiles per instruction)
// 4-stage cp.async K=32 pipeline, padded 80B rows (conflict-free ldmatrix).
// N packing: n = 4*h + gate -> in-register LSTM epilogue via lane-pair shuffle.
// ===========================================================================

#define B_ROWS   65536
#define DIN      256
#define HDIM     512
#define K_TOTAL  768
#define N_TOTAL  2048

#define TM   128            // CTA M tile
#define TN   256            // CTA N tile = 64 h * 4 gates

#define FB_KC       32
#define FB_STAGES   4
#define FB_ROWB     80                      // 64B data + 16B pad
#define FB_ATILEB   (TM * FB_ROWB)          // 10240
#define FB_BTILEB   (TN * FB_ROWB)          // 20480
#define FB_STAGEB   (FB_ATILEB + FB_BTILEB) // 30720
#define FB_NSTEPS   (K_TOTAL / FB_KC)       // 24

#define OFF_BIAS    64                      // 256 floats: [64, 1088)
#define OFF_TILES   2048
#define SMEM_TOTAL  (OFF_TILES + FB_STAGES * FB_STAGEB)   // 124928

// f16 scratch
__device__ __align__(128) __half g_A[(size_t)B_ROWS * K_TOTAL];   // 96 MB
__device__ __align__(128) __half g_Bw[(size_t)N_TOTAL * K_TOTAL]; // 3 MB

// ---------------------------------------------------------------------------
// helpers
// ---------------------------------------------------------------------------
__device__ __forceinline__ uint32_t smem_u32(const void* p) {
    return (uint32_t)__cvta_generic_to_shared(p);
}
__device__ __forceinline__ void cp_async16(uint32_t sdst, const void* gsrc) {
    asm volatile("cp.async.cg.shared.global [%0], [%1], 16;\n"
                 :: "r"(sdst), "l"(__cvta_generic_to_global(gsrc)));
}
__device__ __forceinline__ float fsig(float x) {
    return __fdividef(1.0f, 1.0f + __expf(-x));
}
__device__ __forceinline__ float ftanh_(float x) {
    float e = __expf(-2.0f * fabsf(x));
    float r = __fdividef(1.0f - e, 1.0f + e);
    return copysignf(r, x);
}
__device__ __forceinline__ void ldsm_x4(uint32_t& r0, uint32_t& r1,
                                        uint32_t& r2, uint32_t& r3, uint32_t a) {
    asm volatile("ldmatrix.sync.aligned.m8n8.x4.shared.b16 {%0,%1,%2,%3}, [%4];\n"
                 : "=r"(r0), "=r"(r1), "=r"(r2), "=r"(r3) : "r"(a));
}
__device__ __forceinline__ void mma16816(float* c, const uint32_t* a,
                                         const uint32_t* b) {
    asm volatile(
        "mma.sync.aligned.m16n8k16.row.col.f32.f16.f16.f32 "
        "{%0,%1,%2,%3}, {%4,%5,%6,%7}, {%8,%9}, {%0,%1,%2,%3};\n"
        : "+f"(c[0]), "+f"(c[1]), "+f"(c[2]), "+f"(c[3])
        : "r"(a[0]), "r"(a[1]), "r"(a[2]), "r"(a[3]), "r"(b[0]), "r"(b[1]));
}

// load one K=32 stage: A 128 rows then B 256 rows, 80B padded rows, 16B chunks
__device__ __forceinline__ void fb_load_stage(uint32_t smem_base, int buf,
                                              int kc0, int tid, int m0, int n0) {
    uint32_t sA = smem_base + OFF_TILES + (uint32_t)buf * FB_STAGEB;
    uint32_t sB = sA + FB_ATILEB;
#pragma unroll
    for (int j = 0; j < 2; j++) {              // A: 512 chunks / 256 threads
        int idx = tid + j * 256;
        int row = idx >> 2, c4 = idx & 3;
        cp_async16(sA + row * FB_ROWB + c4 * 16,
                   g_A + (size_t)(m0 + row) * K_TOTAL + kc0 + c4 * 8);
    }
#pragma unroll
    for (int j = 0; j < 4; j++) {              // B: 1024 chunks / 256 threads
        int idx = tid + j * 256;
        int row = idx >> 2, c4 = idx & 3;
        cp_async16(sB + row * FB_ROWB + c4 * 16,
                   g_Bw + (size_t)(n0 + row) * K_TOTAL + kc0 + c4 * 8);
    }
    asm volatile("cp.async.commit_group;\n" ::: "memory");
}

// ---------------------------------------------------------------------------
// prep kernels: fp32 -> f16 packing
// ---------------------------------------------------------------------------
__global__ void __launch_bounds__(256) prep_A(const float* __restrict__ x,
                                              const float* __restrict__ h) {
    size_t i  = (size_t)blockIdx.x * blockDim.x + threadIdx.x;
    size_t e0 = i * 8;
    int b = (int)(e0 / K_TOTAL);
    int k = (int)(e0 % K_TOTAL);
    const float* src = (k < DIN) ? (x + (size_t)b * DIN + k)
                                 : (h + (size_t)b * HDIM + (k - DIN));
    float4 f0 = ((const float4*)src)[0];
    float4 f1 = ((const float4*)src)[1];
    __half2 p0 = __floats2half2_rn(f0.x, f0.y);
    __half2 p1 = __floats2half2_rn(f0.z, f0.w);
    __half2 p2 = __floats2half2_rn(f1.x, f1.y);
    __half2 p3 = __floats2half2_rn(f1.z, f1.w);
    uint4 o;
    o.x = *reinterpret_cast<unsigned*>(&p0);
    o.y = *reinterpret_cast<unsigned*>(&p1);
    o.z = *reinterpret_cast<unsigned*>(&p2);
    o.w = *reinterpret_cast<unsigned*>(&p3);
    *reinterpret_cast<uint4*>(g_A + e0) = o;
}

__global__ void __launch_bounds__(256) prep_B(const float* __restrict__ U,
                                              const float* __restrict__ W) {
    int t = blockIdx.x * blockDim.x + threadIdx.x;
    int k = t % K_TOTAL;
    int n = t / K_TOTAL;
    int g = n & 3;
    int hh = n >> 2;
    float v = (k < DIN) ? U[((size_t)g * DIN + k) * HDIM + hh]
                        : W[((size_t)g * HDIM + (k - DIN)) * HDIM + hh];
    g_Bw[(size_t)n * K_TOTAL + k] = __float2half_rn(v);
}

// ---------------------------------------------------------------------------
// main kernel: 128x256 GEMM tile + fused LSTM epilogue
// ---------------------------------------------------------------------------
__global__ void __launch_bounds__(256, 1)
lstm_main(const float* __restrict__ c_old, const float* __restrict__ bU,
          const float* __restrict__ bW, float* __restrict__ out) {
    extern __shared__ __align__(1024) char smem[];
    uint32_t smem_base = smem_u32(smem);
    int tid  = threadIdx.x;
    int wid  = tid >> 5;
    int lane = tid & 31;
    int h0 = blockIdx.x * (TN / 4);          // 64 h per CTA
    int n0 = blockIdx.x * TN;
    int m0 = blockIdx.y * TM;

    // bias table indexed by local n column (n = 4*h + gate)
    float* sbias = reinterpret_cast<float*>(smem + OFF_BIAS);
    {
        int g  = tid & 3;
        int hg = h0 + (tid >> 2);
        sbias[tid] = bU[g * HDIM + hg] + bW[g * HDIM + hg];
    }

    int warpM = wid >> 2;                    // 0..1   (64 rows each)
    int warpN = wid & 3;                     // 0..3   (64 cols each)

    float acc[4][8][4];
#pragma unroll
    for (int a = 0; a < 4; a++)
#pragma unroll
        for (int b = 0; b < 8; b++)
#pragma unroll
            for (int c = 0; c < 4; c++) acc[a][b][c] = 0.0f;

    // ldmatrix lane address components
    // A (x4): lanes 0-15 rows, lanes 16-31 k-high half
    int rowA  = warpM * 64 + (lane & 15);            // + ma*16
    int colAb = (lane >> 4) * 16;                    // 0 or 16 bytes
    // B (x4, two n-tiles per fetch): lanes 0-7 (na even, k-lo), 8-15 (na even,
    // k-hi), 16-23 (na odd, k-lo), 24-31 (na odd, k-hi)
    int rowB  = warpN * 64 + ((lane >> 4) << 3) + (lane & 7);   // + na2*16
    int colBb = ((lane >> 3) & 1) * 16;

    // prologue: 3 stages in flight
    fb_load_stage(smem_base, 0, 0, tid, m0, n0);
    fb_load_stage(smem_base, 1, FB_KC, tid, m0, n0);
    fb_load_stage(smem_base, 2, 2 * FB_KC, tid, m0, n0);

#pragma unroll 1
    for (int i = 0; i < FB_NSTEPS; i++) {
        if (i <= FB_NSTEPS - 3)
            asm volatile("cp.async.wait_group 2;\n" ::: "memory");
        else if (i == FB_NSTEPS - 2)
            asm volatile("cp.async.wait_group 1;\n" ::: "memory");
        else
            asm volatile("cp.async.wait_group 0;\n" ::: "memory");
        __syncthreads();

        if (i + 3 < FB_NSTEPS)
            fb_load_stage(smem_base, (i + 3) & 3, (i + 3) * FB_KC, tid, m0, n0);

        uint32_t sA = smem_base + OFF_TILES + (uint32_t)(i & 3) * FB_STAGEB;
        uint32_t sB = sA + FB_ATILEB;
#pragma unroll
        for (int kk = 0; kk < 2; kk++) {
            uint32_t afr[4][4], bfr[8][2];
#pragma unroll
            for (int ma = 0; ma < 4; ma++)
                ldsm_x4(afr[ma][0], afr[ma][1], afr[ma][2], afr[ma][3],
                        sA + (rowA + ma * 16) * FB_ROWB + kk * 32 + colAb);
#pragma unroll
            for (int na2 = 0; na2 < 4; na2++)
                ldsm_x4(bfr[2 * na2][0], bfr[2 * na2][1],
                        bfr[2 * na2 + 1][0], bfr[2 * na2 + 1][1],
                        sB + (rowB + na2 * 16) * FB_ROWB + kk * 32 + colBb);
#pragma unroll
            for (int ma = 0; ma < 4; ma++)
#pragma unroll
                for (int na = 0; na < 8; na++)
                    mma16816(acc[ma][na], afr[ma], bfr[na]);
        }
    }
    __syncthreads();

    // fused epilogue: lane-pair shuffle reunites 4 gates per (row, h)
    {
        bool odd = lane & 1;
        int r_base = m0 + warpM * 64 + (lane >> 2) + (odd ? 8 : 0);
        int h_base = h0 + warpN * 16 + ((lane & 3) >> 1);
        float* outc = out + (size_t)B_ROWS * HDIM;

#pragma unroll
        for (int ma = 0; ma < 4; ma++) {
            int row = r_base + ma * 16;
#pragma unroll
            for (int na = 0; na < 8; na++) {
                int nl = warpN * 64 + na * 8 + (lane & 3) * 2;
                float d0 = acc[ma][na][0] + sbias[nl];
                float d1 = acc[ma][na][1] + sbias[nl + 1];
                float d2 = acc[ma][na][2] + sbias[nl];
                float d3 = acc[ma][na][3] + sbias[nl + 1];
                float e0 = __shfl_xor_sync(0xffffffffu, d0, 1);
                float e1 = __shfl_xor_sync(0xffffffffu, d1, 1);
                float e2 = __shfl_xor_sync(0xffffffffu, d2, 1);
                float e3 = __shfl_xor_sync(0xffffffffu, d3, 1);
                float gi = odd ? e2 : d0;
                float gf = odd ? e3 : d1;
                float go = odd ? d2 : e0;
                float gc = odd ? d3 : e1;
                int h = h_base + na * 2;
                float co = c_old[(size_t)row * HDIM + h];
                float it = fsig(gi), ft = fsig(gf), ot = fsig(go), ct = ftanh_(gc);
                float cc = fmaf(it, ct, ft * co);
                out[(size_t)row * HDIM + h]  = ot * ftanh_(cc);
                outc[(size_t)row * HDIM + h] = cc;
            }
        }
    }
}

// ---------------------------------------------------------------------------
// kernel_launch
// inputs: 0=input_x, 1=h_old, 2=c_old, 3=U, 4=bU, 5=W, 6=bW
// output: [h_new | c_new] fp32, 2*65536*512
// ---------------------------------------------------------------------------
extern "C" void kernel_launch(void* const* d_in, const int* in_sizes, int n_in,
                              void* d_out, int out_size) {
    const float* x    = (const float*)d_in[0];
    const float* hold = (const float*)d_in[1];
    const float* cold = (const float*)d_in[2];
    const float* U    = (const float*)d_in[3];
    const float* bU   = (const float*)d_in[4];
    const float* W    = (const float*)d_in[5];
    const float* bW   = (const float*)d_in[6];
    float* out = (float*)d_out;

    cudaFuncSetAttribute(lstm_main, cudaFuncAttributeMaxDynamicSharedMemorySize,
                         SMEM_TOTAL);

    {   // pack A = [x | h] -> f16
        size_t n8 = (size_t)B_ROWS * K_TOTAL / 8;
        prep_A<<<(unsigned)(n8 / 256), 256>>>(x, hold);
    }
    {   // pack Bw[n][k], n = 4*h + gate -> f16
        int nt = N_TOTAL * K_TOTAL;
        prep_B<<<nt / 256, 256>>>(U, W);
    }

    dim3 grid(N_TOTAL / TN, B_ROWS / TM, 1);   // (8, 512)
    lstm_main<<<grid, 256, SMEM_TOTAL>>>(cold, bU, bW, out);
}

// round 7
// speedup vs baseline: 1.7503x; 1.1344x over previous
#include <cuda_runtime.h>
#include <cuda_fp16.h>
#include <cstdint>

// ===========================================================================
// LSTM cell = one fused f16 GEMM  g = [x|h] @ Wcat^T  (M=65536, N=2048, K=768)
// + fused gate epilogue -> h_new, c_new.
//
// R7 = R3 (known-good 388.7us: CTA 128x128, 8 warps, warp 64x32, 4-stage
// cp.async KC=32 pipeline) + two deltas:
//   1. MUFU.TANH epilogue: tanh.approx.f32; sigmoid = 0.5+0.5*tanh(x/2)
//      -> 5 MUFU/output (was 10) and no divides.
//   2. __launch_bounds__(256, 2): cap 128 regs -> 2 CTAs/SM co-residency so
//      one CTA's epilogue/prologue hides under the other's HMMA mainloop.
// Main loop is at the mma.sync HMMA ceiling (~1024 MAC/cyc/SM); these deltas
// attack the remaining non-tensor slack.
// ===========================================================================

#define B_ROWS   65536
#define DIN      256
#define HDIM     512
#define K_TOTAL  768
#define N_TOTAL  2048

#define TM   128            // CTA M tile
#define TN   128            // CTA N tile = 32 h * 4 gates

#define FB_KC       32
#define FB_STAGES   4
#define FB_ROWB     80                      // 64B data + 16B pad
#define FB_TILEB    (128 * FB_ROWB)         // 10240 per operand tile
#define FB_STAGEB   (2 * FB_TILEB)          // 20480
#define FB_NSTEPS   (K_TOTAL / FB_KC)       // 24

#define OFF_BIAS    64
#define OFF_TILES   1024
#define SMEM_TOTAL  (OFF_TILES + FB_STAGES * FB_STAGEB)   // 82944 -> 2 CTAs/SM

// f16 scratch
__device__ __align__(128) __half g_A[(size_t)B_ROWS * K_TOTAL];   // 96 MB
__device__ __align__(128) __half g_Bw[(size_t)N_TOTAL * K_TOTAL]; // 3 MB

// ---------------------------------------------------------------------------
// helpers
// ---------------------------------------------------------------------------
__device__ __forceinline__ uint32_t smem_u32(const void* p) {
    return (uint32_t)__cvta_generic_to_shared(p);
}
__device__ __forceinline__ void cp_async16(uint32_t sdst, const void* gsrc) {
    asm volatile("cp.async.cg.shared.global [%0], [%1], 16;\n"
                 :: "r"(sdst), "l"(__cvta_generic_to_global(gsrc)));
}
__device__ __forceinline__ float ftanh_(float x) {
    float y;
    asm("tanh.approx.f32 %0, %1;\n" : "=f"(y) : "f"(x));
    return y;
}
__device__ __forceinline__ float fsig(float x) {
    // sigmoid(x) = 0.5 + 0.5 * tanh(0.5 * x)   (1 MUFU + 2 FMA)
    return fmaf(0.5f, ftanh_(0.5f * x), 0.5f);
}
__device__ __forceinline__ void ldsm_x4(uint32_t& r0, uint32_t& r1,
                                        uint32_t& r2, uint32_t& r3, uint32_t a) {
    asm volatile("ldmatrix.sync.aligned.m8n8.x4.shared.b16 {%0,%1,%2,%3}, [%4];\n"
                 : "=r"(r0), "=r"(r1), "=r"(r2), "=r"(r3) : "r"(a));
}
__device__ __forceinline__ void ldsm_x2(uint32_t& r0, uint32_t& r1, uint32_t a) {
    asm volatile("ldmatrix.sync.aligned.m8n8.x2.shared.b16 {%0,%1}, [%2];\n"
                 : "=r"(r0), "=r"(r1) : "r"(a));
}
__device__ __forceinline__ void mma16816(float* c, const uint32_t* a,
                                         const uint32_t* b) {
    asm volatile(
        "mma.sync.aligned.m16n8k16.row.col.f32.f16.f16.f32 "
        "{%0,%1,%2,%3}, {%4,%5,%6,%7}, {%8,%9}, {%0,%1,%2,%3};\n"
        : "+f"(c[0]), "+f"(c[1]), "+f"(c[2]), "+f"(c[3])
        : "r"(a[0]), "r"(a[1]), "r"(a[2]), "r"(a[3]), "r"(b[0]), "r"(b[1]));
}

// load one K=32 stage: A 128 rows + B 128 rows, 80B padded rows, 16B chunks
__device__ __forceinline__ void fb_load_stage(uint32_t smem_base, int buf,
                                              int kc0, int tid, int m0, int n0) {
    uint32_t sA = smem_base + OFF_TILES + (uint32_t)buf * FB_STAGEB;
    uint32_t sB = sA + FB_TILEB;
#pragma unroll
    for (int j = 0; j < 2; j++) {
        int idx = tid + j * 256;              // 0..511
        int row = idx >> 2, c4 = idx & 3;
        cp_async16(sA + row * FB_ROWB + c4 * 16,
                   g_A + (size_t)(m0 + row) * K_TOTAL + kc0 + c4 * 8);
        cp_async16(sB + row * FB_ROWB + c4 * 16,
                   g_Bw + (size_t)(n0 + row) * K_TOTAL + kc0 + c4 * 8);
    }
    asm volatile("cp.async.commit_group;\n" ::: "memory");
}

// ---------------------------------------------------------------------------
// prep kernels: fp32 -> f16 packing
// ---------------------------------------------------------------------------
__global__ void __launch_bounds__(256) prep_A(const float* __restrict__ x,
                                              const float* __restrict__ h) {
    size_t i  = (size_t)blockIdx.x * blockDim.x + threadIdx.x;
    size_t e0 = i * 8;
    int b = (int)(e0 / K_TOTAL);
    int k = (int)(e0 % K_TOTAL);
    const float* src = (k < DIN) ? (x + (size_t)b * DIN + k)
                                 : (h + (size_t)b * HDIM + (k - DIN));
    float4 f0 = ((const float4*)src)[0];
    float4 f1 = ((const float4*)src)[1];
    __half2 p0 = __floats2half2_rn(f0.x, f0.y);
    __half2 p1 = __floats2half2_rn(f0.z, f0.w);
    __half2 p2 = __floats2half2_rn(f1.x, f1.y);
    __half2 p3 = __floats2half2_rn(f1.z, f1.w);
    uint4 o;
    o.x = *reinterpret_cast<unsigned*>(&p0);
    o.y = *reinterpret_cast<unsigned*>(&p1);
    o.z = *reinterpret_cast<unsigned*>(&p2);
    o.w = *reinterpret_cast<unsigned*>(&p3);
    *reinterpret_cast<uint4*>(g_A + e0) = o;
}

__global__ void __launch_bounds__(256) prep_B(const float* __restrict__ U,
                                              const float* __restrict__ W) {
    int t = blockIdx.x * blockDim.x + threadIdx.x;
    int k = t % K_TOTAL;
    int n = t / K_TOTAL;
    int g = n & 3;
    int hh = n >> 2;
    float v = (k < DIN) ? U[((size_t)g * DIN + k) * HDIM + hh]
                        : W[((size_t)g * HDIM + (k - DIN)) * HDIM + hh];
    g_Bw[(size_t)n * K_TOTAL + k] = __float2half_rn(v);
}

// ---------------------------------------------------------------------------
// main kernel: 128x128 GEMM tile + fused LSTM epilogue
// ---------------------------------------------------------------------------
__global__ void __launch_bounds__(256, 2)
lstm_main(const float* __restrict__ c_old, const float* __restrict__ bU,
          const float* __restrict__ bW, float* __restrict__ out) {
    extern __shared__ __align__(1024) char smem[];
    uint32_t smem_base = smem_u32(smem);
    int tid  = threadIdx.x;
    int wid  = tid >> 5;
    int lane = tid & 31;
    int h0 = blockIdx.x * (TN / 4);          // 32 h per CTA; n-block fastest
    int n0 = blockIdx.x * TN;
    int m0 = blockIdx.y * TM;

    // bias table indexed by local n column (n = 4*h + gate)
    float* sbias = reinterpret_cast<float*>(smem + OFF_BIAS);
    if (tid < TN) {
        int g  = tid & 3;
        int hg = h0 + (tid >> 2);
        sbias[tid] = bU[g * HDIM + hg] + bW[g * HDIM + hg];
    }

    int warpM = wid >> 2;                    // 0..1   (64 rows each)
    int warpN = wid & 3;                     // 0..3   (32 cols each)

    float acc[4][4][4];
#pragma unroll
    for (int a = 0; a < 4; a++)
#pragma unroll
        for (int b = 0; b < 4; b++)
#pragma unroll
            for (int c = 0; c < 4; c++) acc[a][b][c] = 0.0f;

    // ldmatrix lane address components
    int rowA  = warpM * 64 + (lane & 15);            // + ma*16
    int colAb = ((lane >> 4) << 3) * 2;              // 0 or 16 bytes
    int l16   = lane & 15;
    int rowB  = warpN * 32 + (l16 & 7);              // + na*8
    int colBb = ((l16 >> 3) & 1) * 16;               // 0 or 16 bytes

    // prologue: 3 stages in flight
    fb_load_stage(smem_base, 0, 0, tid, m0, n0);
    fb_load_stage(smem_base, 1, FB_KC, tid, m0, n0);
    fb_load_stage(smem_base, 2, 2 * FB_KC, tid, m0, n0);

#pragma unroll 1
    for (int i = 0; i < FB_NSTEPS; i++) {
        if (i <= FB_NSTEPS - 3)
            asm volatile("cp.async.wait_group 2;\n" ::: "memory");
        else if (i == FB_NSTEPS - 2)
            asm volatile("cp.async.wait_group 1;\n" ::: "memory");
        else
            asm volatile("cp.async.wait_group 0;\n" ::: "memory");
        __syncthreads();

        if (i + 3 < FB_NSTEPS)
            fb_load_stage(smem_base, (i + 3) & 3, (i + 3) * FB_KC, tid, m0, n0);

        uint32_t sA = smem_base + OFF_TILES + (uint32_t)(i & 3) * FB_STAGEB;
        uint32_t sB = sA + FB_TILEB;
#pragma unroll
        for (int kk = 0; kk < 2; kk++) {
            uint32_t afr[4][4], bfr[4][2];
#pragma unroll
            for (int ma = 0; ma < 4; ma++)
                ldsm_x4(afr[ma][0], afr[ma][1], afr[ma][2], afr[ma][3],
                        sA + (rowA + ma * 16) * FB_ROWB + kk * 32 + colAb);
#pragma unroll
            for (int na = 0; na < 4; na++)
                ldsm_x2(bfr[na][0], bfr[na][1],
                        sB + (rowB + na * 8) * FB_ROWB + kk * 32 + colBb);
#pragma unroll
            for (int ma = 0; ma < 4; ma++)
#pragma unroll
                for (int na = 0; na < 4; na++)
                    mma16816(acc[ma][na], afr[ma], bfr[na]);
        }
    }
    __syncthreads();

    // fused epilogue: lane-pair shuffle reunites 4 gates per (row, h)
    {
        bool odd = lane & 1;
        int r_base = m0 + warpM * 64 + (lane >> 2) + (odd ? 8 : 0);
        int h_base = h0 + warpN * 8 + ((lane & 3) >> 1);
        float* outc = out + (size_t)B_ROWS * HDIM;

#pragma unroll
        for (int ma = 0; ma < 4; ma++) {
            int row = r_base + ma * 16;
#pragma unroll
            for (int na = 0; na < 4; na++) {
                int nl = warpN * 32 + na * 8 + (lane & 3) * 2;
                float d0 = acc[ma][na][0] + sbias[nl];
                float d1 = acc[ma][na][1] + sbias[nl + 1];
                float d2 = acc[ma][na][2] + sbias[nl];
                float d3 = acc[ma][na][3] + sbias[nl + 1];
                float e0 = __shfl_xor_sync(0xffffffffu, d0, 1);
                float e1 = __shfl_xor_sync(0xffffffffu, d1, 1);
                float e2 = __shfl_xor_sync(0xffffffffu, d2, 1);
                float e3 = __shfl_xor_sync(0xffffffffu, d3, 1);
                float gi = odd ? e2 : d0;
                float gf = odd ? e3 : d1;
                float go = odd ? d2 : e0;
                float gc = odd ? d3 : e1;
                int h = h_base + na * 2;
                float co = c_old[(size_t)row * HDIM + h];
                float it = fsig(gi), ft = fsig(gf), ot = fsig(go), ct = ftanh_(gc);
                float cc = fmaf(it, ct, ft * co);
                out[(size_t)row * HDIM + h]  = ot * ftanh_(cc);
                outc[(size_t)row * HDIM + h] = cc;
            }
        }
    }
}

// ---------------------------------------------------------------------------
// kernel_launch
// inputs: 0=input_x, 1=h_old, 2=c_old, 3=U, 4=bU, 5=W, 6=bW
// output: [h_new | c_new] fp32, 2*65536*512
// ---------------------------------------------------------------------------
extern "C" void kernel_launch(void* const* d_in, const int* in_sizes, int n_in,
                              void* d_out, int out_size) {
    const float* x    = (const float*)d_in[0];
    const float* hold = (const float*)d_in[1];
    const float* cold = (const float*)d_in[2];
    const float* U    = (const float*)d_in[3];
    const float* bU   = (const float*)d_in[4];
    const float* W    = (const float*)d_in[5];
    const float* bW   = (const float*)d_in[6];
    float* out = (float*)d_out;

    cudaFuncSetAttribute(lstm_main, cudaFuncAttributeMaxDynamicSharedMemorySize,
                         SMEM_TOTAL);

    {   // pack Bw[n][k], n = 4*h + gate -> f16 (small, first)
        int nt = N_TOTAL * K_TOTAL;
        prep_B<<<nt / 256, 256>>>(U, W);
    }
    {   // pack A = [x | h] -> f16
        size_t n8 = (size_t)B_ROWS * K_TOTAL / 8;
        prep_A<<<(unsigned)(n8 / 256), 256>>>(x, hold);
    }

    dim3 grid(N_TOTAL / TN, B_ROWS / TM, 1);   // (16, 512)
    lstm_main<<<grid, 256, SMEM_TOTAL>>>(cold, bU, bW, out);
}